// round 16
// baseline (speedup 1.0000x reference)
#include <cuda_runtime.h>
#include <cuda_fp16.h>
#include <cstdint>

#define BATCH 8192
#define OUT_N 4096
#define KD    4096
#define SHOTS 1000

#define BM 256
#define BN 128
#define BK 64                       // K elems per stage (=128 bytes per row)
#define STAGES 4
#define KBLK (KD / BK)              // 64
#define NITER KBLK                  // 64
#define STAGE_BYTES (BM * 128 + BN * 128)   // 49152
#define SMEM_ALLOC (STAGES * STAGE_BYTES + 1024)   // 197632

// prep kernel block ranges
#define PX 4096
#define PW 2048
#define PE 1024                     // 8 rows per block (warp per row)

// ---- scratch (no device allocation allowed -> __device__ globals) ----
__device__ __align__(256) __half g_x[BATCH * KD];
__device__ __align__(256) __half g_w[OUT_N * KD];
__device__ float g_expect[BATCH];

// ---------------------------------------------------------------------------
__device__ __forceinline__ uint32_t smem_to_u32(const void* p) {
    uint32_t a;
    asm("{ .reg .u64 t; cvta.to.shared.u64 t, %1; cvt.u32.u64 %0, t; }" : "=r"(a) : "l"(p));
    return a;
}
#define SWZ(o) ((o) ^ (((o) >> 3) & 0x70))

__device__ __forceinline__ void cp_async16(uint32_t dst, const void* src) {
    asm volatile("cp.async.cg.shared.global [%0], [%1], 16;" :: "r"(dst), "l"(src));
}
#define CP_COMMIT() asm volatile("cp.async.commit_group;" ::: "memory")
#define CP_WAIT2()  asm volatile("cp.async.wait_group 2;"  ::: "memory")

__device__ __forceinline__ void ldm_x4(uint32_t* r, uint32_t addr) {
    asm volatile("ldmatrix.sync.aligned.m8n8.x4.shared.b16 {%0,%1,%2,%3}, [%4];"
                 : "=r"(r[0]), "=r"(r[1]), "=r"(r[2]), "=r"(r[3]) : "r"(addr));
}

__device__ __forceinline__ void mma16816(float* c, const uint32_t* a, uint32_t b0, uint32_t b1) {
    asm volatile(
        "mma.sync.aligned.m16n8k16.row.col.f32.f16.f16.f32 "
        "{%0,%1,%2,%3}, {%4,%5,%6,%7}, {%8,%9}, {%0,%1,%2,%3};"
        : "+f"(c[0]), "+f"(c[1]), "+f"(c[2]), "+f"(c[3])
        : "r"(a[0]), "r"(a[1]), "r"(a[2]), "r"(a[3]), "r"(b0), "r"(b1));
}

__device__ __forceinline__ uint2 cvt4(float4 v) {
    __half2 a = __halves2half2(__float2half_rn(v.x), __float2half_rn(v.y));
    __half2 b = __halves2half2(__float2half_rn(v.z), __float2half_rn(v.w));
    uint2 hv; hv.x = *(const uint32_t*)&a; hv.y = *(const uint32_t*)&b;
    return hv;
}

// ---------------------------------------------------------------------------
// fused prep: fp32->fp16 for x and W (16B stores), per-row outcome expectation
// ---------------------------------------------------------------------------
__global__ __launch_bounds__(256) void prep_kernel(const float4* __restrict__ x,
                                                   const float4* __restrict__ w,
                                                   const int4* __restrict__ q) {
    const int b = blockIdx.x;
    const int tid = threadIdx.x;
    if (b < PX) {
        const int n8 = BATCH * KD / 8;
        uint4* dst = reinterpret_cast<uint4*>(g_x);
        for (int i = b * 256 + tid; i < n8; i += PX * 256) {
            uint2 lo = cvt4(x[2 * i]);
            uint2 hi = cvt4(x[2 * i + 1]);
            uint4 o; o.x = lo.x; o.y = lo.y; o.z = hi.x; o.w = hi.y;
            dst[i] = o;
        }
    } else if (b < PX + PW) {
        const int bb = b - PX;
        const int n8 = OUT_N * KD / 8;
        uint4* dst = reinterpret_cast<uint4*>(g_w);
        for (int i = bb * 256 + tid; i < n8; i += PW * 256) {
            uint2 lo = cvt4(w[2 * i]);
            uint2 hi = cvt4(w[2 * i + 1]);
            uint4 o; o.x = lo.x; o.y = lo.y; o.z = hi.x; o.w = hi.y;
            dst[i] = o;
        }
    } else {
        const int row  = (b - PX - PW) * 8 + (tid >> 5);   // warp per row
        const int lane = tid & 31;
        const int4* p = q + (size_t)row * (SHOTS / 4);     // 250 int4 per row
        int sum = 0;
        for (int i = lane; i < SHOTS / 4; i += 32) {
            int4 v = p[i];
            sum += v.x + v.y + v.z + v.w;
        }
        #pragma unroll
        for (int off = 16; off; off >>= 1) sum += __shfl_down_sync(0xffffffffu, sum, off);
        if (lane == 0)
            g_expect[row] = (float)sum * (1.0f / (15.0f * (float)SHOTS));
    }
}

// ---------------------------------------------------------------------------
// mma.sync fp16 GEMM: out = x W^T + bias + expect
// 256x128 tile, BK=64, 4-stage cp.async pipeline, 16 warps (8x2), 32x64/warp,
// 512 threads, 1 CTA/SM (4 warps/SMSP). Warp-level config identical to R15;
// 25% less fill traffic per FLOP + deeper pipeline.
// MMA nest mi-outer/ni-inner (A reuse over 8 consecutive HMMAs) — keep order.
// ---------------------------------------------------------------------------
__global__ __launch_bounds__(512, 1) void gemm_kernel(const float* __restrict__ bias,
                                                      float* __restrict__ out) {
    extern __shared__ char smem_raw[];
    uint32_t sbase = (smem_to_u32(smem_raw) + 1023u) & ~1023u;
    const int tid  = threadIdx.x;
    const int wid  = tid >> 5;
    const int lane = tid & 31;

    // --- rasterization with GROUP_M supergrouping ---
    const int num_pid_n = OUT_N / BN;   // 32
    const int num_pid_m = BATCH / BM;   // 32
    const int GROUP_M = 8;
    int pid = blockIdx.x;
    int num_in_group = GROUP_M * num_pid_n;
    int group_id = pid / num_in_group;
    int first_m = group_id * GROUP_M;
    int gsz = min(num_pid_m - first_m, GROUP_M);
    int pid_m = first_m + (pid % gsz);
    int pid_n = (pid % num_in_group) / gsz;
    const int bm = pid_m * BM;
    const int bn = pid_n * BN;

    const int wm = wid & 7;     // 0..7 : 32-row band
    const int wn = wid >> 3;    // 0..1 : 64-col band

    // --- loader: 3072 chunks/stage, 6 per thread; rows lr8+64u ---
    const int lr8 = tid >> 3;             // 0..63
    const int lc  = tid & 7;              // 0..7
    const char* gA = (const char*)g_x + ((size_t)(bm + lr8) * KD + lc * 8) * 2;
    const char* gB = (const char*)g_w + ((size_t)(bn + lr8) * KD + lc * 8) * 2;

    auto issue_loads = [&](int slot, uint32_t kboff) {
        const uint32_t sb = sbase + slot * STAGE_BYTES;
        #pragma unroll
        for (int u = 0; u < 4; ++u) {
            uint32_t so = SWZ((uint32_t)((lr8 + 64 * u) * 128 + lc * 16));
            cp_async16(sb + so, gA + (uint32_t)(64 * u) * (KD * 2) + kboff);
        }
        #pragma unroll
        for (int u = 0; u < 2; ++u) {
            uint32_t so = SWZ((uint32_t)((lr8 + 64 * u) * 128 + lc * 16));
            cp_async16(sb + (uint32_t)(BM * 128) + so,
                       gB + (uint32_t)(64 * u) * (KD * 2) + kboff);
        }
        CP_COMMIT();
    };

    // --- per-lane ldmatrix base offsets ---
    const int g  = lane >> 3;
    const int lr = lane & 7;
    const int a_row_base = wm * 32 + lr + (g & 1) * 8;   // + mi*16
    const int a_col_base = (g >> 1) * 16;                // + ks*32
    const int b_row_base = wn * 64 + lr + (g >> 1) * 8;  // + np*16
    const int b_col_base = (g & 1) * 16;                 // + ks*32

    float acc[2][8][4];
    #pragma unroll
    for (int mi = 0; mi < 2; mi++)
        #pragma unroll
        for (int ni = 0; ni < 8; ni++)
            #pragma unroll
            for (int k = 0; k < 4; k++) acc[mi][ni][k] = 0.0f;

    issue_loads(0, 0);
    issue_loads(1, BK * 2);
    issue_loads(2, 2 * BK * 2);

    int slot = 0;                 // stage being consumed
    int nslot = 3;                // stage to fill next
    uint32_t nkboff = 3 * BK * 2; // K-byte offset of next fill

    for (int it = 0; it < NITER; ++it) {
        CP_WAIT2();
        __syncthreads();

        if (it + 3 < NITER) {
            issue_loads(nslot, nkboff);
            nslot = (nslot == STAGES - 1) ? 0 : nslot + 1;
            nkboff += BK * 2;
        } else {
            CP_COMMIT();          // empty group keeps wait count valid
        }

        const uint32_t sA = sbase + slot * STAGE_BYTES;
        const uint32_t sB = sA + BM * 128;
        slot = (slot == STAGES - 1) ? 0 : slot + 1;

        #pragma unroll
        for (int ks = 0; ks < 4; ++ks) {
            uint32_t a[2][4];
            #pragma unroll
            for (int mi = 0; mi < 2; ++mi) {
                uint32_t off = (uint32_t)((a_row_base + mi * 16) * 128 +
                                          ks * 32 + a_col_base);
                ldm_x4(a[mi], sA + SWZ(off));
            }
            uint32_t b[4][4];
            #pragma unroll
            for (int np = 0; np < 4; ++np) {
                uint32_t off = (uint32_t)((b_row_base + np * 16) * 128 +
                                          ks * 32 + b_col_base);
                ldm_x4(b[np], sB + SWZ(off));
            }
            #pragma unroll
            for (int mi = 0; mi < 2; ++mi)
                #pragma unroll
                for (int ni = 0; ni < 8; ++ni)
                    mma16816(acc[mi][ni], a[mi],
                             b[ni >> 1][2 * (ni & 1)], b[ni >> 1][2 * (ni & 1) + 1]);
        }
    }

    // --- epilogue: + bias[col] + expect[row] ---
    float bv[16];
    #pragma unroll
    for (int ni = 0; ni < 8; ++ni) {
        const int c = bn + wn * 64 + ni * 8 + (lane & 3) * 2;
        bv[2 * ni]     = __ldg(&bias[c]);
        bv[2 * ni + 1] = __ldg(&bias[c + 1]);
    }

    #pragma unroll
    for (int mi = 0; mi < 2; ++mi) {
        const int r0 = bm + wm * 32 + mi * 16 + (lane >> 2);
        const float e0 = g_expect[r0];
        const float e1 = g_expect[r0 + 8];
        float* o0 = out + (size_t)r0 * OUT_N;
        float* o1 = out + (size_t)(r0 + 8) * OUT_N;
        #pragma unroll
        for (int ni = 0; ni < 8; ++ni) {
            const int c = bn + wn * 64 + ni * 8 + (lane & 3) * 2;
            float2 v0, v1;
            v0.x = acc[mi][ni][0] + bv[2 * ni]     + e0;
            v0.y = acc[mi][ni][1] + bv[2 * ni + 1] + e0;
            v1.x = acc[mi][ni][2] + bv[2 * ni]     + e1;
            v1.y = acc[mi][ni][3] + bv[2 * ni + 1] + e1;
            *(float2*)(o0 + c) = v0;
            *(float2*)(o1 + c) = v1;
        }
    }
}

// ---------------------------------------------------------------------------
extern "C" void kernel_launch(void* const* d_in, const int* in_sizes, int n_in,
                              void* d_out, int out_size) {
    const float* x    = (const float*)d_in[0];   // [8192, 4096]
    const float* W    = (const float*)d_in[1];   // [4096, 4096]
    const float* bias = (const float*)d_in[2];   // [4096]
    const int*   q    = (const int*)d_in[3];     // [8192, 1000]
    float* out = (float*)d_out;                  // [8192, 4096]

    cudaFuncSetAttribute(gemm_kernel, cudaFuncAttributeMaxDynamicSharedMemorySize, SMEM_ALLOC);

    prep_kernel<<<PX + PW + PE, 256>>>((const float4*)x, (const float4*)W,
                                       (const int4*)q);

    const int grid = (BATCH / BM) * (OUT_N / BN);   // 1024
    gemm_kernel<<<grid, 512, SMEM_ALLOC>>>(bias, out);
}

// round 17
// speedup vs baseline: 1.1067x; 1.1067x over previous
#include <cuda_runtime.h>
#include <cuda_fp16.h>
#include <cstdint>

#define BATCH 8192
#define OUT_N 4096
#define KD    4096
#define SHOTS 1000

#define BM 128
#define BN 128
#define BK 64                       // K elems per stage (=128 bytes per row)
#define STAGES 3
#define KBLK (KD / BK)              // 64
#define NITER KBLK                  // 64
#define STAGE_BYTES (BM * 128 + BN * 128)   // 32768
#define SMEM_ALLOC (STAGES * STAGE_BYTES + 1024)   // 99328

// prep kernel block ranges
#define PX 4096
#define PW 2048
#define PE 1024                     // 8 rows per block (warp per row)

// ---- scratch (no device allocation allowed -> __device__ globals) ----
__device__ __align__(256) __half g_x[BATCH * KD];
__device__ __align__(256) __half g_w[OUT_N * KD];
__device__ float g_expect[BATCH];

// ---------------------------------------------------------------------------
__device__ __forceinline__ uint32_t smem_to_u32(const void* p) {
    uint32_t a;
    asm("{ .reg .u64 t; cvta.to.shared.u64 t, %1; cvt.u32.u64 %0, t; }" : "=r"(a) : "l"(p));
    return a;
}
#define SWZ(o) ((o) ^ (((o) >> 3) & 0x70))

__device__ __forceinline__ void cp_async16(uint32_t dst, const void* src) {
    asm volatile("cp.async.cg.shared.global [%0], [%1], 16;" :: "r"(dst), "l"(src));
}
#define CP_COMMIT() asm volatile("cp.async.commit_group;" ::: "memory")
#define CP_WAIT1()  asm volatile("cp.async.wait_group 1;"  ::: "memory")

__device__ __forceinline__ void ldm_x4(uint32_t* r, uint32_t addr) {
    asm volatile("ldmatrix.sync.aligned.m8n8.x4.shared.b16 {%0,%1,%2,%3}, [%4];"
                 : "=r"(r[0]), "=r"(r[1]), "=r"(r[2]), "=r"(r[3]) : "r"(addr));
}

__device__ __forceinline__ void mma16816(float* c, const uint32_t* a, uint32_t b0, uint32_t b1) {
    asm volatile(
        "mma.sync.aligned.m16n8k16.row.col.f32.f16.f16.f32 "
        "{%0,%1,%2,%3}, {%4,%5,%6,%7}, {%8,%9}, {%0,%1,%2,%3};"
        : "+f"(c[0]), "+f"(c[1]), "+f"(c[2]), "+f"(c[3])
        : "r"(a[0]), "r"(a[1]), "r"(a[2]), "r"(a[3]), "r"(b0), "r"(b1));
}

__device__ __forceinline__ uint2 cvt4(float4 v) {
    __half2 a = __halves2half2(__float2half_rn(v.x), __float2half_rn(v.y));
    __half2 b = __halves2half2(__float2half_rn(v.z), __float2half_rn(v.w));
    uint2 hv; hv.x = *(const uint32_t*)&a; hv.y = *(const uint32_t*)&b;
    return hv;
}

// ---------------------------------------------------------------------------
// fused prep: fp32->fp16 for x and W (16B stores), per-row outcome expectation
// ---------------------------------------------------------------------------
__global__ __launch_bounds__(256) void prep_kernel(const float4* __restrict__ x,
                                                   const float4* __restrict__ w,
                                                   const int4* __restrict__ q) {
    const int b = blockIdx.x;
    const int tid = threadIdx.x;
    if (b < PX) {
        const int n8 = BATCH * KD / 8;
        uint4* dst = reinterpret_cast<uint4*>(g_x);
        for (int i = b * 256 + tid; i < n8; i += PX * 256) {
            uint2 lo = cvt4(x[2 * i]);
            uint2 hi = cvt4(x[2 * i + 1]);
            uint4 o; o.x = lo.x; o.y = lo.y; o.z = hi.x; o.w = hi.y;
            dst[i] = o;
        }
    } else if (b < PX + PW) {
        const int bb = b - PX;
        const int n8 = OUT_N * KD / 8;
        uint4* dst = reinterpret_cast<uint4*>(g_w);
        for (int i = bb * 256 + tid; i < n8; i += PW * 256) {
            uint2 lo = cvt4(w[2 * i]);
            uint2 hi = cvt4(w[2 * i + 1]);
            uint4 o; o.x = lo.x; o.y = lo.y; o.z = hi.x; o.w = hi.y;
            dst[i] = o;
        }
    } else {
        const int row  = (b - PX - PW) * 8 + (tid >> 5);   // warp per row
        const int lane = tid & 31;
        const int4* p = q + (size_t)row * (SHOTS / 4);     // 250 int4 per row
        int sum = 0;
        for (int i = lane; i < SHOTS / 4; i += 32) {
            int4 v = p[i];
            sum += v.x + v.y + v.z + v.w;
        }
        #pragma unroll
        for (int off = 16; off; off >>= 1) sum += __shfl_down_sync(0xffffffffu, sum, off);
        if (lane == 0)
            g_expect[row] = (float)sum * (1.0f / (15.0f * (float)SHOTS));
    }
}

// ---------------------------------------------------------------------------
// mma.sync fp16 GEMM: out = x W^T + bias + expect
// 128x128 tile, BK=64, 3-stage cp.async pipeline, 8 warps (4x2), 32x64/warp,
// 256 threads, 2 CTAs/SM (R15 config). Next-stage cp.async issue is DEFERRED
// into the MMA body (after ks=1) so it doesn't collide with the LDSM burst
// at iteration start. MMA nest mi-outer/ni-inner — keep order.
// ---------------------------------------------------------------------------
__global__ __launch_bounds__(256, 2) void gemm_kernel(const float* __restrict__ bias,
                                                      float* __restrict__ out) {
    extern __shared__ char smem_raw[];
    uint32_t sbase = (smem_to_u32(smem_raw) + 1023u) & ~1023u;
    const int tid  = threadIdx.x;
    const int wid  = tid >> 5;
    const int lane = tid & 31;

    // --- rasterization with GROUP_M supergrouping ---
    const int num_pid_n = OUT_N / BN;   // 32
    const int num_pid_m = BATCH / BM;   // 64
    const int GROUP_M = 8;
    int pid = blockIdx.x;
    int num_in_group = GROUP_M * num_pid_n;
    int group_id = pid / num_in_group;
    int first_m = group_id * GROUP_M;
    int gsz = min(num_pid_m - first_m, GROUP_M);
    int pid_m = first_m + (pid % gsz);
    int pid_n = (pid % num_in_group) / gsz;
    const int bm = pid_m * BM;
    const int bn = pid_n * BN;

    const int wm = wid & 3;     // 0..3 : 32-row band
    const int wn = wid >> 2;    // 0..1 : 64-col band

    // --- loader: 2048 chunks/stage, 8 per thread; rows lr8+32u ---
    const int lr8 = tid >> 3;             // 0..31
    const int lc  = tid & 7;              // 0..7
    const char* gA = (const char*)g_x + ((size_t)(bm + lr8) * KD + lc * 8) * 2;
    const char* gB = (const char*)g_w + ((size_t)(bn + lr8) * KD + lc * 8) * 2;

    auto issue_loads = [&](int slot, uint32_t kboff) {
        const uint32_t sb = sbase + slot * STAGE_BYTES;
        #pragma unroll
        for (int u = 0; u < 4; ++u) {
            uint32_t so = SWZ((uint32_t)((lr8 + 32 * u) * 128 + lc * 16));
            cp_async16(sb + so, gA + (uint32_t)(32 * u) * (KD * 2) + kboff);
        }
        #pragma unroll
        for (int u = 0; u < 4; ++u) {
            uint32_t so = SWZ((uint32_t)((lr8 + 32 * u) * 128 + lc * 16));
            cp_async16(sb + (uint32_t)(BM * 128) + so,
                       gB + (uint32_t)(32 * u) * (KD * 2) + kboff);
        }
        CP_COMMIT();
    };

    // --- per-lane ldmatrix base offsets ---
    const int g  = lane >> 3;
    const int lr = lane & 7;
    const int a_row_base = wm * 32 + lr + (g & 1) * 8;   // + mi*16
    const int a_col_base = (g >> 1) * 16;                // + ks*32
    const int b_row_base = wn * 64 + lr + (g >> 1) * 8;  // + np*16
    const int b_col_base = (g & 1) * 16;                 // + ks*32

    float acc[2][8][4];
    #pragma unroll
    for (int mi = 0; mi < 2; mi++)
        #pragma unroll
        for (int ni = 0; ni < 8; ni++)
            #pragma unroll
            for (int k = 0; k < 4; k++) acc[mi][ni][k] = 0.0f;

    issue_loads(0, 0);
    issue_loads(1, BK * 2);

    int slot = 0;                 // stage being consumed
    int nslot = 2;                // stage to fill next
    uint32_t nkboff = 2 * BK * 2; // K-byte offset of next fill

    for (int it = 0; it < NITER; ++it) {
        CP_WAIT1();
        __syncthreads();

        const bool do_load = (it + 2 < NITER);

        const uint32_t sA = sbase + slot * STAGE_BYTES;
        const uint32_t sB = sA + BM * 128;
        slot = (slot == STAGES - 1) ? 0 : slot + 1;

        #pragma unroll
        for (int ks = 0; ks < 4; ++ks) {
            uint32_t a[2][4];
            #pragma unroll
            for (int mi = 0; mi < 2; ++mi) {
                uint32_t off = (uint32_t)((a_row_base + mi * 16) * 128 +
                                          ks * 32 + a_col_base);
                ldm_x4(a[mi], sA + SWZ(off));
            }
            uint32_t b[4][4];
            #pragma unroll
            for (int np = 0; np < 4; ++np) {
                uint32_t off = (uint32_t)((b_row_base + np * 16) * 128 +
                                          ks * 32 + b_col_base);
                ldm_x4(b[np], sB + SWZ(off));
            }
            #pragma unroll
            for (int mi = 0; mi < 2; ++mi)
                #pragma unroll
                for (int ni = 0; ni < 8; ++ni)
                    mma16816(acc[mi][ni], a[mi],
                             b[ni >> 1][2 * (ni & 1)], b[ni >> 1][2 * (ni & 1) + 1]);

            // Deferred next-stage load issue: after ks=1, while tensor pipe
            // is busy and LSU is idle (not colliding with iteration-start LDSMs).
            if (ks == 1) {
                if (do_load) issue_loads(nslot, nkboff);
                else         CP_COMMIT();   // keep wait_group count valid
            }
        }

        if (do_load) {
            nslot = (nslot == STAGES - 1) ? 0 : nslot + 1;
            nkboff += BK * 2;
        }
    }

    // --- epilogue: + bias[col] + expect[row] ---
    float bv[16];
    #pragma unroll
    for (int ni = 0; ni < 8; ++ni) {
        const int c = bn + wn * 64 + ni * 8 + (lane & 3) * 2;
        bv[2 * ni]     = __ldg(&bias[c]);
        bv[2 * ni + 1] = __ldg(&bias[c + 1]);
    }

    #pragma unroll
    for (int mi = 0; mi < 2; ++mi) {
        const int r0 = bm + wm * 32 + mi * 16 + (lane >> 2);
        const float e0 = g_expect[r0];
        const float e1 = g_expect[r0 + 8];
        float* o0 = out + (size_t)r0 * OUT_N;
        float* o1 = out + (size_t)(r0 + 8) * OUT_N;
        #pragma unroll
        for (int ni = 0; ni < 8; ++ni) {
            const int c = bn + wn * 64 + ni * 8 + (lane & 3) * 2;
            float2 v0, v1;
            v0.x = acc[mi][ni][0] + bv[2 * ni]     + e0;
            v0.y = acc[mi][ni][1] + bv[2 * ni + 1] + e0;
            v1.x = acc[mi][ni][2] + bv[2 * ni]     + e1;
            v1.y = acc[mi][ni][3] + bv[2 * ni + 1] + e1;
            *(float2*)(o0 + c) = v0;
            *(float2*)(o1 + c) = v1;
        }
    }
}

// ---------------------------------------------------------------------------
extern "C" void kernel_launch(void* const* d_in, const int* in_sizes, int n_in,
                              void* d_out, int out_size) {
    const float* x    = (const float*)d_in[0];   // [8192, 4096]
    const float* W    = (const float*)d_in[1];   // [4096, 4096]
    const float* bias = (const float*)d_in[2];   // [4096]
    const int*   q    = (const int*)d_in[3];     // [8192, 1000]
    float* out = (float*)d_out;                  // [8192, 4096]

    cudaFuncSetAttribute(gemm_kernel, cudaFuncAttributeMaxDynamicSharedMemorySize, SMEM_ALLOC);

    prep_kernel<<<PX + PW + PE, 256>>>((const float4*)x, (const float4*)W,
                                       (const int4*)q);

    const int grid = (BATCH / BM) * (OUT_N / BN);   // 2048
    gemm_kernel<<<grid, 256, SMEM_ALLOC>>>(bias, out);
}